// round 1
// baseline (speedup 1.0000x reference)
#include <cuda_runtime.h>

#define EDGES  1600000
#define NODES  50000
#define NGRAPH 16
#define KSLOT  8
#define HID    32

// ---------------- scratch (static device allocations; no cudaMalloc) ----------------
__device__ int   g_is64;
__device__ int   g_src[EDGES];
__device__ int   g_dst[EDGES];
__device__ int   g_batch[NODES];
__device__ float g_HS[NODES * HID];     // sum of silu(layer1) per dst node
__device__ float g_CNT[NODES];          // in-degree (float)
__device__ float g_H[NODES * HID];      // node embedding h
__device__ float g_S[NODES * KSLOT];    // softmax assignment s
__device__ float g_POOL[NGRAPH * KSLOT * HID];
__device__ float g_Z[NGRAPH * KSLOT * 4];

__device__ __forceinline__ float siluf(float a) {
    // a * sigmoid(a) = a / (1 + exp(-a)); __expf/__fdividef accurate to ~2 ulp
    return __fdividef(a, 1.0f + __expf(-a));
}

// ---------------- dtype detection: int64 vs int32 edge_index ----------------
__global__ void k_detect(const unsigned int* __restrict__ ei) {
    if (threadIdx.x == 0) {
        int is64 = 1;
        for (int i = 1; i < 64; i += 2) {
            if (ei[i] != 0u) { is64 = 0; break; }
        }
        g_is64 = is64;
    }
}

// ---------------- prep: index convert + zero accumulators ----------------
// grid = EDGES/256 blocks of 256 (EDGES % 256 == 0). NODES*HID == EDGES.
__global__ void k_prep(const void* __restrict__ ei, const void* __restrict__ batch) {
    int i = blockIdx.x * blockDim.x + threadIdx.x;
    int is64 = g_is64;
    if (is64) {
        const long long* q = (const long long*)ei;
        g_src[i] = (int)q[i];
        g_dst[i] = (int)q[EDGES + i];
    } else {
        const int* q = (const int*)ei;
        g_src[i] = q[i];
        g_dst[i] = q[EDGES + i];
    }
    g_HS[i] = 0.0f;
    if (i < NODES) {
        g_batch[i] = is64 ? (int)((const long long*)batch)[i]
                          : ((const int*)batch)[i];
        g_CNT[i] = 0.0f;
    }
    if (i < NGRAPH * KSLOT * HID) g_POOL[i] = 0.0f;
}

// ---------------- edge kernel: layer1 + silu + scatter-add ----------------
__global__ void __launch_bounds__(256) k_edge(const float* __restrict__ x,
                                              const float* __restrict__ pos,
                                              const float* __restrict__ w1,
                                              const float* __restrict__ b1) {
    __shared__ __align__(16) float sw[9 * HID];
    __shared__ __align__(16) float sb[HID];
    for (int i = threadIdx.x; i < 9 * HID; i += 256) sw[i] = w1[i];
    if (threadIdx.x < HID) sb[threadIdx.x] = b1[threadIdx.x];
    __syncthreads();

    int e = blockIdx.x * 256 + threadIdx.x;   // grid covers EDGES exactly
    int s = g_src[e];
    int d = g_dst[e];

    float dx = __ldg(pos + 3 * s + 0) - __ldg(pos + 3 * d + 0);
    float dy = __ldg(pos + 3 * s + 1) - __ldg(pos + 3 * d + 1);
    float dz = __ldg(pos + 3 * s + 2) - __ldg(pos + 3 * d + 2);
    float dist = sqrtf(dx * dx + dy * dy + dz * dz);

    float4 xd = __ldg((const float4*)(x + 4 * (size_t)d));
    float4 xs = __ldg((const float4*)(x + 4 * (size_t)s));
    float in9[9] = { xd.x, xd.y, xd.z, xd.w, xs.x, xs.y, xs.z, xs.w, dist };

    float acc[HID];
#pragma unroll
    for (int j = 0; j < HID; j++) acc[j] = sb[j];
#pragma unroll
    for (int i = 0; i < 9; i++) {
        float xi = in9[i];
#pragma unroll
        for (int j = 0; j < HID; j++) acc[j] = fmaf(xi, sw[i * HID + j], acc[j]);
    }

    float* hs = g_HS + (size_t)d * HID;
#pragma unroll
    for (int c = 0; c < 8; c++) {
        float4 v;
        v.x = siluf(acc[4 * c + 0]);
        v.y = siluf(acc[4 * c + 1]);
        v.z = siluf(acc[4 * c + 2]);
        v.w = siluf(acc[4 * c + 3]);
        atomicAdd(reinterpret_cast<float4*>(hs + 4 * c), v);  // sm_90+ vector RED
    }
    atomicAdd(g_CNT + d, 1.0f);
}

// ---------------- node kernel: h = (HS @ W2)/cnt + b2 ; s = softmax(h@pw+pb) ----------------
__global__ void __launch_bounds__(256) k_node(const float* __restrict__ w2,
                                              const float* __restrict__ b2,
                                              const float* __restrict__ pw,
                                              const float* __restrict__ pb) {
    __shared__ __align__(16) float sw2[HID * HID];
    __shared__ float sb2[HID];
    __shared__ __align__(16) float spw[HID * KSLOT];
    __shared__ float spb[KSLOT];
    for (int i = threadIdx.x; i < HID * HID; i += 256) sw2[i] = w2[i];
    for (int i = threadIdx.x; i < HID * KSLOT; i += 256) spw[i] = pw[i];
    if (threadIdx.x < HID)   sb2[threadIdx.x] = b2[threadIdx.x];
    if (threadIdx.x < KSLOT) spb[threadIdx.x] = pb[threadIdx.x];
    __syncthreads();

    int n = blockIdx.x * 256 + threadIdx.x;
    if (n >= NODES) return;

    float cnt = g_CNT[n];
    float inv = 1.0f / fmaxf(cnt, 1.0f);
    float bsc = (cnt > 0.0f) ? 1.0f : 0.0f;

    float h[HID];
#pragma unroll
    for (int j = 0; j < HID; j++) h[j] = 0.0f;

    const float4* hsp = (const float4*)(g_HS + (size_t)n * HID);
#pragma unroll 1
    for (int c = 0; c < 8; c++) {
        float4 v = __ldg(hsp + c);
#pragma unroll
        for (int j = 0; j < HID; j++) {
            h[j] = fmaf(v.x, sw2[(4 * c + 0) * HID + j], h[j]);
            h[j] = fmaf(v.y, sw2[(4 * c + 1) * HID + j], h[j]);
            h[j] = fmaf(v.z, sw2[(4 * c + 2) * HID + j], h[j]);
            h[j] = fmaf(v.w, sw2[(4 * c + 3) * HID + j], h[j]);
        }
    }
#pragma unroll
    for (int j = 0; j < HID; j++) h[j] = h[j] * inv + bsc * sb2[j];

    float4* Hp = (float4*)(g_H + (size_t)n * HID);
#pragma unroll
    for (int c = 0; c < 8; c++)
        Hp[c] = make_float4(h[4 * c + 0], h[4 * c + 1], h[4 * c + 2], h[4 * c + 3]);

    float l[KSLOT];
#pragma unroll
    for (int k = 0; k < KSLOT; k++) l[k] = spb[k];
#pragma unroll
    for (int j = 0; j < HID; j++) {
        float hj = h[j];
#pragma unroll
        for (int k = 0; k < KSLOT; k++) l[k] = fmaf(hj, spw[j * KSLOT + k], l[k]);
    }
    float m = l[0];
#pragma unroll
    for (int k = 1; k < KSLOT; k++) m = fmaxf(m, l[k]);
    float ex[KSLOT];
    float sum = 0.0f;
#pragma unroll
    for (int k = 0; k < KSLOT; k++) { ex[k] = __expf(l[k] - m); sum += ex[k]; }
    float isum = __fdividef(1.0f, sum);

    float4* Sp = (float4*)(g_S + (size_t)n * KSLOT);
    Sp[0] = make_float4(ex[0] * isum, ex[1] * isum, ex[2] * isum, ex[3] * isum);
    Sp[1] = make_float4(ex[4] * isum, ex[5] * isum, ex[6] * isum, ex[7] * isum);
}

// ---------------- pooling: pooled[b,k,j] = sum_{batch[n]=b} s[n,k]*h[n,j] ----------------
// grid = 64 blocks (16 graphs x 4 slices), 256 threads = (k,j) pairs
__global__ void __launch_bounds__(256) k_pool() {
    int b = blockIdx.x & 15;
    int slice = blockIdx.x >> 4;

    int lo = 0, hi = NODES;
    while (lo < hi) { int m = (lo + hi) >> 1; if (g_batch[m] < b) lo = m + 1; else hi = m; }
    int start = lo;
    lo = start; hi = NODES;
    while (lo < hi) { int m = (lo + hi) >> 1; if (g_batch[m] < b + 1) lo = m + 1; else hi = m; }
    int end = lo;

    int cnt = end - start;
    int s0 = start + (cnt * slice) / 4;
    int s1 = start + (cnt * (slice + 1)) / 4;

    int k = threadIdx.x >> 5;
    int j = threadIdx.x & 31;

    float acc = 0.0f;
#pragma unroll 4
    for (int n = s0; n < s1; n++)
        acc = fmaf(__ldg(g_S + (size_t)n * KSLOT + k), __ldg(g_H + (size_t)n * HID + j), acc);

    atomicAdd(&g_POOL[(b * KSLOT + k) * HID + j], acc);
}

// ---------------- z = pooled @ toz_w + toz_b  (16*8*4 outputs) ----------------
__global__ void k_z(const float* __restrict__ tw, const float* __restrict__ tb) {
    int t = threadIdx.x;               // 512 threads
    int b = t >> 5;
    int k = (t >> 2) & 7;
    int d = t & 3;
    float acc = tb[d];
#pragma unroll
    for (int j = 0; j < HID; j++)
        acc = fmaf(g_POOL[b * 256 + k * 32 + j], tw[j * 4 + d], acc);
    g_Z[t] = acc;   // layout: b*32 + k*4 + d
}

// ---------------- decode: recon[b,n,:] = silu(q@W1+b1)@W2+b2, q = s[n]·z[b] ----------------
__global__ void __launch_bounds__(128) k_dec(const float* __restrict__ w1,
                                             const float* __restrict__ b1,
                                             const float* __restrict__ w2,
                                             const float* __restrict__ b2,
                                             float* __restrict__ out) {
    __shared__ __align__(16) float sz[NGRAPH * KSLOT * 4];   // 512
    __shared__ __align__(16) float sw1[128];                 // transposed [j][d]
    __shared__ float sb1[32];
    __shared__ __align__(16) float sw2[128];                 // [j][d]
    __shared__ float sb2v[4];

    int t = threadIdx.x;
    for (int i = t; i < 512; i += 128) sz[i] = g_Z[i];
    sw1[t] = w1[(t & 3) * 32 + (t >> 2)];  // w1 is [4][32]; store as [j][4]
    sw2[t] = w2[t];
    if (t < 32) sb1[t] = b1[t];
    if (t < 4)  sb2v[t] = b2[t];
    __syncthreads();

    int n = blockIdx.x * 128 + t;
    if (n >= NODES) return;

    float4 sa = *(const float4*)(g_S + (size_t)n * KSLOT);
    float4 sbv = *(const float4*)(g_S + (size_t)n * KSLOT + 4);
    float s[8] = { sa.x, sa.y, sa.z, sa.w, sbv.x, sbv.y, sbv.z, sbv.w };

#pragma unroll 1
    for (int b = 0; b < NGRAPH; b++) {
        float q0 = 0.f, q1 = 0.f, q2 = 0.f, q3 = 0.f;
#pragma unroll
        for (int k = 0; k < 8; k++) {
            float4 zv = *(const float4*)&sz[(b * 8 + k) * 4];
            q0 = fmaf(s[k], zv.x, q0);
            q1 = fmaf(s[k], zv.y, q1);
            q2 = fmaf(s[k], zv.z, q2);
            q3 = fmaf(s[k], zv.w, q3);
        }
        float o0 = sb2v[0], o1 = sb2v[1], o2 = sb2v[2], o3 = sb2v[3];
#pragma unroll
        for (int j = 0; j < 32; j++) {
            float4 wc = *(const float4*)&sw1[j * 4];
            float tt = sb1[j];
            tt = fmaf(q0, wc.x, tt);
            tt = fmaf(q1, wc.y, tt);
            tt = fmaf(q2, wc.z, tt);
            tt = fmaf(q3, wc.w, tt);
            tt = siluf(tt);
            float4 wr = *(const float4*)&sw2[j * 4];
            o0 = fmaf(tt, wr.x, o0);
            o1 = fmaf(tt, wr.y, o1);
            o2 = fmaf(tt, wr.z, o2);
            o3 = fmaf(tt, wr.w, o3);
        }
        *(float4*)(out + ((size_t)b * NODES + n) * 4) = make_float4(o0, o1, o2, o3);
    }
}

// ---------------- launch ----------------
extern "C" void kernel_launch(void* const* d_in, const int* in_sizes, int n_in,
                              void* d_out, int out_size) {
    const float* x      = (const float*)d_in[0];
    const float* pos    = (const float*)d_in[1];
    const void*  ei     = d_in[2];
    const void*  batch  = d_in[3];
    const float* enc_w1 = (const float*)d_in[4];
    const float* enc_b1 = (const float*)d_in[5];
    const float* enc_w2 = (const float*)d_in[6];
    const float* enc_b2 = (const float*)d_in[7];
    const float* pool_w = (const float*)d_in[8];
    const float* pool_b = (const float*)d_in[9];
    const float* toz_w  = (const float*)d_in[10];
    const float* toz_b  = (const float*)d_in[11];
    const float* dec_w1 = (const float*)d_in[12];
    const float* dec_b1 = (const float*)d_in[13];
    const float* dec_w2 = (const float*)d_in[14];
    const float* dec_b2 = (const float*)d_in[15];
    float* out = (float*)d_out;

    k_detect<<<1, 32>>>((const unsigned int*)ei);
    k_prep<<<EDGES / 256, 256>>>(ei, batch);
    k_edge<<<EDGES / 256, 256>>>(x, pos, enc_w1, enc_b1);
    k_node<<<(NODES + 255) / 256, 256>>>(enc_w2, enc_b2, pool_w, pool_b);
    k_pool<<<64, 256>>>();
    k_z<<<1, 512>>>(toz_w, toz_b);
    k_dec<<<(NODES + 127) / 128, 128>>>(dec_w1, dec_b1, dec_w2, dec_b2, out);
}